// round 6
// baseline (speedup 1.0000x reference)
#include <cuda_runtime.h>
#include <cuda_bf16.h>

#define N_NODESC 20000
#define N_EDGESC 320000
#define IN_FC    256
#define OUT_FC   64
#define HEADSC   4
#define ALPHAC   0.1f
#define CAPC     64   // bucket capacity per node (Poisson(16); max ~45)

// ---------------- scratch (static device globals; no allocation) ----------------
// g_ST layout: [dir][node][head][64]; dir0 = S rows (x1@Ws), dir1 = T rows (x2@Wt)
__device__ float g_ST[2 * N_NODESC * HEADSC * OUT_FC];   // ~41 MB
__device__ float g_P1[N_NODESC * 8];   // [node][z]; z<4: S-side, z>=4: T-side (vs a1)
__device__ float g_P2[N_NODESC * 8];   // same vs a2
__device__ int g_degT[N_NODESC], g_degS[N_NODESC];
__device__ int g_nbrT[N_NODESC * CAPC];   // tgt buckets: src nodes
__device__ int g_nbrS[N_NODESC * CAPC];   // src buckets: tgt nodes
// normalized attention weights, bucket-ordered: [node][slot][head]
__device__ float g_WS[N_NODESC * CAPC * HEADSC];   // dir0 (h_st)
__device__ float g_WT[N_NODESC * CAPC * HEADSC];   // dir1 (h_ts)

// ---------------- packed f32x2 helpers ----------------
__device__ __forceinline__ unsigned long long pack2(float a, float b) {
    unsigned long long r;
    asm("mov.b64 %0, {%1, %2};" : "=l"(r) : "f"(a), "f"(b));
    return r;
}
__device__ __forceinline__ void fma2(unsigned long long& d,
                                     unsigned long long a, unsigned long long b) {
    asm("fma.rn.f32x2 %0, %1, %2, %0;" : "+l"(d) : "l"(a), "l"(b));
}
__device__ __forceinline__ float2 unpack2(unsigned long long v) {
    float2 r;
    asm("mov.b64 {%0, %1}, %2;" : "=f"(r.x), "=f"(r.y) : "l"(v));
    return r;
}

// ---------------- kernel 0: zero degree counters ----------------
__global__ void zero_kernel() {
    int i = blockIdx.x * blockDim.x + threadIdx.x;
    if (i < N_NODESC) { g_degT[i] = 0; g_degS[i] = 0; }
}

// ---------------- kernel 1: bucket-CSR fill ----------------
__global__ void fill_kernel(const int* __restrict__ src, const int* __restrict__ tgt) {
    int e = blockIdx.x * blockDim.x + threadIdx.x;
    if (e >= N_EDGESC) return;
    int t = tgt[e], s = src[e];
    int st = atomicAdd(&g_degT[t], 1);
    g_nbrT[(t << 6) + st] = s;
    int ss = atomicAdd(&g_degS[s], 1);
    g_nbrS[(s << 6) + ss] = t;
}

// ---------------- kernel 2: fused 8-way GEMM (f32x2, reg-prefetch) + projections ----
// grid = (ceil(N/128), 8), block 256. Tile 128x64, K-chunk 32, micro 4x8.
__global__ void __launch_bounds__(256, 3) gemm_kernel(
    const float* __restrict__ x1, const float* __restrict__ x2,
    const float* __restrict__ Ws, const float* __restrict__ Wt,
    const float* __restrict__ a1, const float* __restrict__ a2)
{
    __shared__ float As[32][132];  // [k][m], padded
    __shared__ float Bs[32][64];   // [k][n]
    __shared__ float sA1[64], sA2[64];
    __shared__ float sP1[128], sP2[128];

    int z = blockIdx.y;
    int head = z & 3, dir = z >> 2;
    const float* X = dir ? x2 : x1;
    const float* W = (dir ? Wt : Ws) + head * IN_FC * OUT_FC;
    int m0 = blockIdx.x * 128;
    int tid = threadIdx.x;
    int mg = tid & 31;
    int ng = tid >> 5;

    if (tid < 128) { sP1[tid] = 0.0f; sP2[tid] = 0.0f; }
    if (tid < 64) {
        int aoff = head * 2 * OUT_FC + dir * OUT_FC + tid;
        sA1[tid] = a1[aoff];
        sA2[tid] = a2[aoff];
    }

    // per-thread load coordinates (constant across chunks)
    int arow[4], akq[4];
    bool aok[4];
#pragma unroll
    for (int j = 0; j < 4; j++) {
        int i = tid + 256 * j;
        arow[j] = i >> 3;
        akq[j] = (i & 7) * 4;
        aok[j] = (m0 + arow[j]) < N_NODESC;
    }
    int bkr[2], bcq[2];
#pragma unroll
    for (int j = 0; j < 2; j++) {
        int i = tid + 256 * j;
        bkr[j] = i >> 4;
        bcq[j] = (i & 15) * 4;
    }

    unsigned long long acc[4][4];
#pragma unroll
    for (int i = 0; i < 4; i++)
#pragma unroll
        for (int j = 0; j < 4; j++) acc[i][j] = 0ULL;

    float4 ra[4], rb[2];
    // prologue: load chunk 0 into registers
#pragma unroll
    for (int j = 0; j < 4; j++)
        ra[j] = aok[j] ? *(const float4*)&X[(size_t)(m0 + arow[j]) * IN_FC + akq[j]]
                       : make_float4(0.f, 0.f, 0.f, 0.f);
#pragma unroll
    for (int j = 0; j < 2; j++)
        rb[j] = *(const float4*)&W[(size_t)bkr[j] * OUT_FC + bcq[j]];

    for (int chunk = 0; chunk < IN_FC / 32; chunk++) {
        // store regs -> smem
#pragma unroll
        for (int j = 0; j < 4; j++) {
            As[akq[j] + 0][arow[j]] = ra[j].x;
            As[akq[j] + 1][arow[j]] = ra[j].y;
            As[akq[j] + 2][arow[j]] = ra[j].z;
            As[akq[j] + 3][arow[j]] = ra[j].w;
        }
#pragma unroll
        for (int j = 0; j < 2; j++)
            *(float4*)&Bs[bkr[j]][bcq[j]] = rb[j];
        __syncthreads();

        // prefetch next chunk into registers (LDG latency hides under compute)
        if (chunk + 1 < IN_FC / 32) {
            int k0 = (chunk + 1) * 32;
#pragma unroll
            for (int j = 0; j < 4; j++)
                ra[j] = aok[j] ? *(const float4*)&X[(size_t)(m0 + arow[j]) * IN_FC + k0 + akq[j]]
                               : make_float4(0.f, 0.f, 0.f, 0.f);
#pragma unroll
            for (int j = 0; j < 2; j++)
                rb[j] = *(const float4*)&W[(size_t)(k0 + bkr[j]) * OUT_FC + bcq[j]];
        }

#pragma unroll 8
        for (int k = 0; k < 32; k++) {
            float4 a0 = *(const float4*)&As[k][mg * 4];
            ulonglong2 bp0 = *(const ulonglong2*)&Bs[k][ng * 8];
            ulonglong2 bp1 = *(const ulonglong2*)&Bs[k][ng * 8 + 4];
            unsigned long long ap[4];
            ap[0] = pack2(a0.x, a0.x); ap[1] = pack2(a0.y, a0.y);
            ap[2] = pack2(a0.z, a0.z); ap[3] = pack2(a0.w, a0.w);
#pragma unroll
            for (int ii = 0; ii < 4; ii++) {
                fma2(acc[ii][0], ap[ii], bp0.x);
                fma2(acc[ii][1], ap[ii], bp0.y);
                fma2(acc[ii][2], ap[ii], bp1.x);
                fma2(acc[ii][3], ap[ii], bp1.y);
            }
        }
        __syncthreads();
    }

    // epilogue: store rows + projection partial sums
    float w10 = sA1[ng * 8 + 0], w11 = sA1[ng * 8 + 1], w12 = sA1[ng * 8 + 2], w13 = sA1[ng * 8 + 3];
    float w14 = sA1[ng * 8 + 4], w15 = sA1[ng * 8 + 5], w16 = sA1[ng * 8 + 6], w17 = sA1[ng * 8 + 7];
    float w20 = sA2[ng * 8 + 0], w21 = sA2[ng * 8 + 1], w22 = sA2[ng * 8 + 2], w23 = sA2[ng * 8 + 3];
    float w24 = sA2[ng * 8 + 4], w25 = sA2[ng * 8 + 5], w26 = sA2[ng * 8 + 6], w27 = sA2[ng * 8 + 7];
#pragma unroll
    for (int ii = 0; ii < 4; ii++) {
        int r = mg * 4 + ii;
        int m = m0 + r;
        float2 c0 = unpack2(acc[ii][0]);
        float2 c1 = unpack2(acc[ii][1]);
        float2 c2 = unpack2(acc[ii][2]);
        float2 c3 = unpack2(acc[ii][3]);
        if (m < N_NODESC) {
            float* o = &g_ST[(((size_t)dir * N_NODESC + m) * HEADSC + head) * OUT_FC + ng * 8];
            *(ulonglong2*)&o[0] = make_ulonglong2(acc[ii][0], acc[ii][1]);
            *(ulonglong2*)&o[4] = make_ulonglong2(acc[ii][2], acc[ii][3]);
        }
        float d1 = c0.x * w10 + c0.y * w11 + c1.x * w12 + c1.y * w13
                 + c2.x * w14 + c2.y * w15 + c3.x * w16 + c3.y * w17;
        float d2 = c0.x * w20 + c0.y * w21 + c1.x * w22 + c1.y * w23
                 + c2.x * w24 + c2.y * w25 + c3.x * w26 + c3.y * w27;
        atomicAdd(&sP1[r], d1);
        atomicAdd(&sP2[r], d2);
    }
    __syncthreads();
    if (tid < 128) {
        int m = m0 + tid;
        if (m < N_NODESC) {
            g_P1[m * 8 + z] = sP1[tid];
            g_P2[m * 8 + z] = sP2[tid];
        }
    }
}

// ---------------- kernel 3: normalized attention weights ----------------
// One warp per (node, dir); lane = (slot 0..7, head 0..3). Two register passes:
// compute exp + denominator, then store alpha = w/den bucket-ordered [slot][head].
__global__ void __launch_bounds__(256) weight_kernel() {
    int gw = (blockIdx.x * 256 + threadIdx.x) >> 5;
    int lane = threadIdx.x & 31;
    int node = gw >> 1, dir = gw & 1;
    if (node >= N_NODESC) return;

    int deg;
    const int* __restrict__ nbr;
    const float* __restrict__ P;
    float* __restrict__ Wout;
    int ooff, poff;
    if (dir == 0) {  // h_st: node=src, weights from P2
        deg = g_degS[node]; nbr = g_nbrS + (node << 6);
        P = g_P2; ooff = 0; poff = 4; Wout = g_WS;
    } else {         // h_ts: node=tgt, weights from P1
        deg = g_degT[node]; nbr = g_nbrT + (node << 6);
        P = g_P1; ooff = 4; poff = 0; Wout = g_WT;
    }
    if (deg == 0) return;

    int sh = lane & 3;   // head
    int se = lane >> 2;  // slot within chunk of 8
    float own = __ldg(&P[node * 8 + ooff + sh]);

    float wreg[8];
    float denp = 0.0f;
#pragma unroll
    for (int it = 0; it < 8; it++) {
        int j = it * 8 + se;
        float w = 0.0f;
        if (j < deg) {
            int nb = __ldg(&nbr[j]);
            float e = own + __ldg(&P[nb * 8 + poff + sh]);
            e = fmaxf(e, ALPHAC * e);   // leaky_relu (alpha>0)
            w = __expf(e);
        }
        wreg[it] = w;
        denp += w;
        if (it * 8 + 8 >= deg) break;
    }
    denp += __shfl_xor_sync(0xFFFFFFFFu, denp, 4);
    denp += __shfl_xor_sync(0xFFFFFFFFu, denp, 8);
    denp += __shfl_xor_sync(0xFFFFFFFFu, denp, 16);
    float inv = (denp > 0.0f) ? (1.0f / denp) : 0.0f;

    float* wb = Wout + ((size_t)node << 8);  // node*CAPC*HEADS
#pragma unroll
    for (int it = 0; it < 8; it++) {
        int j = it * 8 + se;
        if (j < deg) wb[(j << 2) + sh] = wreg[it] * inv;
        if (it * 8 + 8 >= deg) break;
    }
}

// ---------------- kernel 4: lean gather aggregation + ELU ----------------
// One warp per (node, dir); lane = (head 0..3, featgrp 0..7) owns 8 contiguous
// floats. Per edge: 2 broadcast LDGs (nbr, alpha) + 2x LDG.128 + 4x fma.f32x2.
__global__ void __launch_bounds__(256) agg_kernel(float* __restrict__ out) {
    int gw = (blockIdx.x * 256 + threadIdx.x) >> 5;
    int lane = threadIdx.x & 31;
    int node = gw >> 1, dir = gw & 1;
    if (node >= N_NODESC) return;

    int deg;
    const int* __restrict__ nbr;
    const float* __restrict__ alph;
    const float* __restrict__ rows;
    if (dir == 0) {  // h_st: gather T rows
        deg = g_degS[node]; nbr = g_nbrS + (node << 6);
        alph = g_WS + ((size_t)node << 8);
        rows = g_ST + (size_t)N_NODESC * (HEADSC * OUT_FC);
    } else {         // h_ts: gather S rows
        deg = g_degT[node]; nbr = g_nbrT + (node << 6);
        alph = g_WT + ((size_t)node << 8);
        rows = g_ST;
    }

    int fh = lane >> 3;
    int laneoff = fh * OUT_FC + (lane & 7) * 8;

    unsigned long long acc[4] = {0ULL, 0ULL, 0ULL, 0ULL};

#pragma unroll 4
    for (int j = 0; j < deg; j++) {
        int nbb = __ldg(&nbr[j]);
        float al = __ldg(&alph[(j << 2) + fh]);
        const float* base = rows + nbb * (HEADSC * OUT_FC) + laneoff;
        ulonglong2 qa = *(const ulonglong2*)(base);
        ulonglong2 qb = *(const ulonglong2*)(base + 4);
        unsigned long long wp = pack2(al, al);
        fma2(acc[0], wp, qa.x);
        fma2(acc[1], wp, qa.y);
        fma2(acc[2], wp, qb.x);
        fma2(acc[3], wp, qb.y);
    }

    float2 f0 = unpack2(acc[0]);
    float2 f1 = unpack2(acc[1]);
    float2 f2 = unpack2(acc[2]);
    float2 f3 = unpack2(acc[3]);
    float r0 = f0.x, r1 = f0.y, r2 = f1.x, r3 = f1.y;
    float r4 = f2.x, r5 = f2.y, r6 = f3.x, r7 = f3.y;
    r0 = (r0 > 0.f) ? r0 : expm1f(r0);
    r1 = (r1 > 0.f) ? r1 : expm1f(r1);
    r2 = (r2 > 0.f) ? r2 : expm1f(r2);
    r3 = (r3 > 0.f) ? r3 : expm1f(r3);
    r4 = (r4 > 0.f) ? r4 : expm1f(r4);
    r5 = (r5 > 0.f) ? r5 : expm1f(r5);
    r6 = (r6 > 0.f) ? r6 : expm1f(r6);
    r7 = (r7 > 0.f) ? r7 : expm1f(r7);

    float* o = out + ((size_t)(dir ? N_NODESC : 0) + node) * (HEADSC * OUT_FC) + laneoff;
    *(float4*)(o)     = make_float4(r0, r1, r2, r3);
    *(float4*)(o + 4) = make_float4(r4, r5, r6, r7);
}

// ---------------- launch ----------------
extern "C" void kernel_launch(void* const* d_in, const int* in_sizes, int n_in,
                              void* d_out, int out_size) {
    const float* x1 = (const float*)d_in[0];
    const float* x2 = (const float*)d_in[1];
    const float* Ws = (const float*)d_in[2];
    const float* Wt = (const float*)d_in[3];
    const float* a1 = (const float*)d_in[4];
    const float* a2 = (const float*)d_in[5];
    const int* tgt  = (const int*)d_in[6];
    const int* src  = (const int*)d_in[7];
    float* out = (float*)d_out;

    zero_kernel<<<(N_NODESC + 255) / 256, 256>>>();
    fill_kernel<<<(N_EDGESC + 255) / 256, 256>>>(src, tgt);

    dim3 gg((N_NODESC + 127) / 128, 8);
    gemm_kernel<<<gg, 256>>>(x1, x2, Ws, Wt, a1, a2);

    weight_kernel<<<(N_NODESC * 2 * 32 + 255) / 256, 256>>>();
    agg_kernel<<<(N_NODESC * 2 * 32 + 255) / 256, 256>>>(out);
}